// round 5
// baseline (speedup 1.0000x reference)
#include <cuda_runtime.h>
#include <math.h>

// ---------------------------------------------------------------------------
// Fully fused StripPooling: pool + mix(BN/GEMM) + sigmoid gate in ONE kernel.
// Grid: 2048 blocks (8 batches x 256 tiles), 256 threads.
// Block (b, tile): tile covers 64 rows x 256 cols of plane bc=b*64+c,
//   c = tile>>2, quarter q4 = tile&3 (rows q4*64 .. q4*64+63) = 4 full h-bins.
// Each block holds its 64KB x-tile (32KB regs + 32KB smem), so x is read from
// DRAM exactly once. Per-batch flag released by the last pooling block after
// it computes the GEMM/BN chain.
// ---------------------------------------------------------------------------

__device__ float g_hp[8192];        // [b][c][p] h-bin means
__device__ float g_vp_part[32768];  // [b][c][quarter][q] w-bin partial sums
__device__ float g_fh[8192];        // [b][c][p]
__device__ float g_fv[8192];        // [b][c][q]
__device__ int   g_cnt[8];          // pool-done counter per batch
__device__ int   g_flag[8];         // mix-done flag per batch
__device__ int   g_done[8];         // gate-done counter per batch (for reset)

__global__ void __launch_bounds__(256, 3) sp_fused_kernel(
    const float*  __restrict__ x,   float* __restrict__ out,
    const float* __restrict__ Wh, const float* __restrict__ bh,
    const float* __restrict__ Wv, const float* __restrict__ bv,
    const float* __restrict__ Wf, const float* __restrict__ bf,
    const float* __restrict__ hg, const float* __restrict__ hb_,
    const float* __restrict__ hm, const float* __restrict__ hv,
    const float* __restrict__ vg, const float* __restrict__ vb,
    const float* __restrict__ vm, const float* __restrict__ vv,
    const float* __restrict__ fg, const float* __restrict__ fb,
    const float* __restrict__ fm, const float* __restrict__ fvr)
{
    __shared__ float4 s_pay[2048];   // 32KB: h-bins 2,3 payload, [k*256+t]
    __shared__ float  s_hp[1024];    // mix scratch [c][p]
    __shared__ float  s_vp[1024];    // mix scratch [c][q]
    __shared__ float  s_h[4];
    __shared__ float  s_w[16];
    __shared__ int    s_last;

    const int bid  = blockIdx.x;          // 0..2047
    const int b    = bid >> 8;            // batch
    const int tile = bid & 255;
    const int c    = tile >> 2;
    const int q4   = tile & 3;
    const int bc   = b * 64 + c;

    const int t    = threadIdx.x;
    const int ry   = t >> 6;               // 0..3
    const int cg   = t & 63;               // float4 column (w-bin = cg>>2)
    const int lane = t & 31;

    const float4* __restrict__ x4 = reinterpret_cast<const float4*>(x);
    float4* __restrict__ out4     = reinterpret_cast<float4*>(out);

    // float4 index of (hb, j): bc*16384 + (q4*64 + hb*16 + ry*4 + j)*64 + cg
    const size_t base = (size_t)bc * 16384 + (size_t)(q4 * 64 + ry * 4) * 64 + cg;

    if (t < 16) s_w[t] = 0.f;
    if (t < 4)  s_h[t] = 0.f;
    __syncthreads();

    // ---- Phase 1: load tile (h-bins 0,1 -> regs; 2,3 -> smem), pool ----
    float4 v[8];
#pragma unroll
    for (int k = 0; k < 8; ++k) {
        const int hb = k >> 2, j = k & 3;
        v[k] = x4[base + (size_t)(hb * 16 + j) * 64];
    }
    float acc[4];
#pragma unroll
    for (int hb = 0; hb < 2; ++hb) {
        float a = 0.f;
#pragma unroll
        for (int j = 0; j < 4; ++j) {
            const float4 u = v[hb * 4 + j];
            a += (u.x + u.y) + (u.z + u.w);
        }
        acc[hb] = a;
    }
#pragma unroll
    for (int hb = 2; hb < 4; ++hb) {
        float a = 0.f;
#pragma unroll
        for (int j = 0; j < 4; ++j) {
            const float4 u = x4[base + (size_t)(hb * 16 + j) * 64];
            a += (u.x + u.y) + (u.z + u.w);
            s_pay[((hb - 2) * 4 + j) * 256 + t] = u;
        }
        acc[hb] = a;
    }

    // h-bin sums: whole warp shares ry; full-warp reduce per hb.
#pragma unroll
    for (int hb = 0; hb < 4; ++hb) {
        float a = acc[hb];
#pragma unroll
        for (int off = 16; off; off >>= 1)
            a += __shfl_down_sync(0xffffffffu, a, off);
        if (lane == 0) atomicAdd(&s_h[hb], a);
    }
    // w-bin partials: 4 consecutive lanes share w-bin cg>>2.
    float w = acc[0] + acc[1] + acc[2] + acc[3];
    w += __shfl_down_sync(0xffffffffu, w, 2);
    w += __shfl_down_sync(0xffffffffu, w, 1);
    if ((lane & 3) == 0) atomicAdd(&s_w[cg >> 2], w);
    __syncthreads();

    if (t < 4)
        g_hp[bc * 16 + q4 * 4 + t] = s_h[t] * (1.0f / 4096.0f);
    if (t < 16)
        g_vp_part[bc * 64 + q4 * 16 + t] = s_w[t];
    __threadfence();
    __syncthreads();

    if (t == 0) {
        const int old = atomicAdd(&g_cnt[b], 1);
        s_last = (old == 255);
    }
    __syncthreads();

    // ---- Phase 2: last block of the batch runs the GEMM/BN chain ----
    if (s_last) {
        for (int i = t; i < 1024; i += 256) {
            s_hp[i] = g_hp[b * 1024 + i];
            const float* vp = g_vp_part + (b * 64 + (i >> 4)) * 64 + (i & 15);
            s_vp[i] = (vp[0] + vp[16] + vp[32] + vp[48]) * (1.0f / 4096.0f);
        }
        __syncthreads();

        float hn[4], vn[4];
#pragma unroll
        for (int k = 0; k < 4; ++k) {
            const int i = t + k * 256;
            const int o = i >> 4, p = i & 15;
            float ah = 0.f, av = 0.f;
#pragma unroll 8
            for (int c2 = 0; c2 < 64; ++c2) {
                ah += Wh[o * 64 + c2] * s_hp[c2 * 16 + p];
                av += Wv[o * 64 + c2] * s_vp[c2 * 16 + p];
            }
            const float invh = hg[o] * rsqrtf(hv[o] + 1e-5f);
            const float invv = vg[o] * rsqrtf(vv[o] + 1e-5f);
            hn[k] = (ah + bh[o]) * invh + (hb_[o] - hm[o] * invh);
            vn[k] = (av + bv[o]) * invv + (vb[o] - vm[o] * invv);
        }
        __syncthreads();
#pragma unroll
        for (int k = 0; k < 4; ++k) {
            s_hp[t + k * 256] = hn[k];
            s_vp[t + k * 256] = vn[k];
        }
        __syncthreads();
#pragma unroll
        for (int k = 0; k < 4; ++k) {
            const int i = t + k * 256;
            const int o = i >> 4, p = i & 15;
            float ah = 0.f, av = 0.f;
#pragma unroll 8
            for (int c2 = 0; c2 < 64; ++c2) {
                ah += Wf[o * 128 + c2]      * s_hp[c2 * 16 + p];
                av += Wf[o * 128 + 64 + c2] * s_vp[c2 * 16 + p];
            }
            const float invf = fg[o] * rsqrtf(fvr[o] + 1e-5f);
            g_fh[b * 1024 + i] = ah * invf;
            g_fv[b * 1024 + i] = (av + bf[o]) * invf + (fb[o] - fm[o] * invf);
        }
        __threadfence();
        __syncthreads();
        if (t == 0) atomicExch(&g_flag[b], 1);
    } else {
        // ---- spin until this batch's mix is published ----
        if (t == 0) {
            while (((volatile int*)g_flag)[b] == 0) __nanosleep(128);
        }
        __syncthreads();
        __threadfence();
    }

    // ---- Phase 3: gate + writeback from held tile ----
    float sg[4];
    {
        const float fvq = __ldg(&g_fv[bc * 16 + (cg >> 2)]);
#pragma unroll
        for (int hb = 0; hb < 4; ++hb) {
            const float z = __ldg(&g_fh[bc * 16 + q4 * 4 + hb]) + fvq;
            sg[hb] = 1.0f / (1.0f + expf(-z));
        }
    }
#pragma unroll
    for (int k = 0; k < 8; ++k) {
        const int hb = k >> 2, j = k & 3;
        float4 u = v[k];
        const float s = sg[hb];
        u.x *= s; u.y *= s; u.z *= s; u.w *= s;
        __stcs(&out4[base + (size_t)(hb * 16 + j) * 64], u);
    }
#pragma unroll
    for (int k = 0; k < 8; ++k) {
        const int hb = 2 + (k >> 2), j = k & 3;
        float4 u = s_pay[k * 256 + t];
        const float s = sg[hb];
        u.x *= s; u.y *= s; u.z *= s; u.w *= s;
        __stcs(&out4[base + (size_t)(hb * 16 + j) * 64], u);
    }

    // ---- Reset per-batch state for the next replay ----
    __threadfence();
    __syncthreads();
    if (t == 0) {
        const int d = atomicAdd(&g_done[b], 1);
        if (d == 255) {
            g_cnt[b]  = 0;
            g_flag[b] = 0;
            __threadfence();
            g_done[b] = 0;
        }
    }
}

// ---------------------------------------------------------------------------
extern "C" void kernel_launch(void* const* d_in, const int* in_sizes, int n_in,
                              void* d_out, int out_size)
{
    const float* x  = (const float*)d_in[0];
    const float* Wh = (const float*)d_in[1];
    const float* bh = (const float*)d_in[2];
    const float* Wv = (const float*)d_in[3];
    const float* bv = (const float*)d_in[4];
    const float* Wf = (const float*)d_in[5];
    const float* bf = (const float*)d_in[6];
    const float* hg = (const float*)d_in[7];
    const float* hb = (const float*)d_in[8];
    const float* hm = (const float*)d_in[9];
    const float* hv = (const float*)d_in[10];
    const float* vg = (const float*)d_in[11];
    const float* vb = (const float*)d_in[12];
    const float* vm = (const float*)d_in[13];
    const float* vv = (const float*)d_in[14];
    const float* fg = (const float*)d_in[15];
    const float* fb = (const float*)d_in[16];
    const float* fm = (const float*)d_in[17];
    const float* fv = (const float*)d_in[18];

    sp_fused_kernel<<<2048, 256>>>(x, (float*)d_out,
                                   Wh, bh, Wv, bv, Wf, bf,
                                   hg, hb, hm, hv,
                                   vg, vb, vm, vv,
                                   fg, fb, fm, fv);
}

// round 6
// speedup vs baseline: 3.1179x; 3.1179x over previous
#include <cuda_runtime.h>
#include <math.h>

// Scratch (allocation-free).
__device__ float g_hp[8192];          // [bc][p]      h-bin means
__device__ float g_vp_part[131072];   // [bc][p][q]   per-h-bin w partial sums
__device__ float g_hpn[8192];         // [b][c][p]    BN_h(conv_h) output
__device__ float g_vpn[8192];         // [b][c][q]    BN_v(conv_v) output
__device__ float g_sig[131072];       // [bc][p][q]   precomputed sigmoids

// ---------------------------------------------------------------------------
// Kernel 1: strip pooling (unchanged from R4: 23.3us measured).
// One block per (plane, h-bin): grid 8192, 128 threads.
// ---------------------------------------------------------------------------
__global__ void __launch_bounds__(128) sp_pool_kernel(const float* __restrict__ x) {
    const int blk = blockIdx.x;           // 0..8191
    const int bc  = blk >> 4;
    const int p   = blk & 15;
    const float4* __restrict__ tile =
        reinterpret_cast<const float4*>(x + (size_t)bc * 65536) + p * 1024;

    const int t    = threadIdx.x;
    const int half = t >> 6;
    const int cg   = t & 63;
    const int lane = t & 31;
    const int wrp  = t >> 5;

    float4 v[8];
#pragma unroll
    for (int j = 0; j < 8; ++j)
        v[j] = tile[(half * 8 + j) * 64 + cg];

    float acc = 0.f;
#pragma unroll
    for (int j = 0; j < 8; ++j)
        acc += (v[j].x + v[j].y) + (v[j].z + v[j].w);

    __shared__ float s_h[4];
    __shared__ float s_w[16];
    if (t < 16) s_w[t] = 0.f;
    __syncthreads();

    float wsum = acc;
    wsum += __shfl_down_sync(0xffffffffu, wsum, 2);
    wsum += __shfl_down_sync(0xffffffffu, wsum, 1);
    if ((lane & 3) == 0) atomicAdd(&s_w[cg >> 2], wsum);

    float hsum = acc;
#pragma unroll
    for (int off = 16; off; off >>= 1)
        hsum += __shfl_down_sync(0xffffffffu, hsum, off);
    if (lane == 0) s_h[wrp] = hsum;
    __syncthreads();

    if (t == 0)
        g_hp[bc * 16 + p] = (s_h[0] + s_h[1] + s_h[2] + s_h[3]) * (1.0f / 4096.0f);
    if (t < 16)
        g_vp_part[bc * 256 + p * 16 + t] = s_w[t];
}

// ---------------------------------------------------------------------------
// Kernel 2a: first linear + BN. 8 blocks x 1024 threads; one output/thread.
// ---------------------------------------------------------------------------
__global__ void __launch_bounds__(1024) sp_mix1_kernel(
    const float* __restrict__ Wh, const float* __restrict__ bh,
    const float* __restrict__ Wv, const float* __restrict__ bv,
    const float* __restrict__ hg, const float* __restrict__ hb,
    const float* __restrict__ hm, const float* __restrict__ hv,
    const float* __restrict__ vg, const float* __restrict__ vb,
    const float* __restrict__ vm, const float* __restrict__ vv)
{
    __shared__ float s_hp[1024];   // [c][p]
    __shared__ float s_vp[1024];   // [c][q]

    const int b = blockIdx.x;
    const int t = threadIdx.x;     // 0..1023

    s_hp[t] = g_hp[b * 1024 + t];
    {
        const int c = t >> 4, q = t & 15;
        const float* vp = g_vp_part + (size_t)(b * 64 + c) * 256 + q;
        float sum = 0.f;
#pragma unroll
        for (int pp = 0; pp < 16; ++pp) sum += vp[pp * 16];
        s_vp[t] = sum * (1.0f / 4096.0f);
    }
    __syncthreads();

    const int o = t >> 4, p = t & 15;
    float ah = 0.f, av = 0.f;
#pragma unroll 8
    for (int c = 0; c < 64; ++c) {
        ah += Wh[o * 64 + c] * s_hp[c * 16 + p];
        av += Wv[o * 64 + c] * s_vp[c * 16 + p];
    }
    const float invh = hg[o] * rsqrtf(hv[o] + 1e-5f);
    const float invv = vg[o] * rsqrtf(vv[o] + 1e-5f);
    g_hpn[b * 1024 + t] = (ah + bh[o]) * invh + (hb[o] - hm[o] * invh);
    g_vpn[b * 1024 + t] = (av + bv[o]) * invv + (vb[o] - vm[o] * invv);
}

// ---------------------------------------------------------------------------
// Kernel 2b: fusion linear + BN + sigmoid table. Grid 64 = 8 batches x
// 8 channel-groups (8 output channels each). 256 threads.
// ---------------------------------------------------------------------------
__global__ void __launch_bounds__(256) sp_mix2_kernel(
    const float* __restrict__ Wf, const float* __restrict__ bf,
    const float* __restrict__ fg, const float* __restrict__ fb,
    const float* __restrict__ fm, const float* __restrict__ fvr)
{
    __shared__ float s_hpn[1024];
    __shared__ float s_vpn[1024];
    __shared__ float s_fh[128];    // [ch][p] for this 8-channel group
    __shared__ float s_fv[128];

    const int b   = blockIdx.x >> 3;
    const int grp = blockIdx.x & 7;
    const int t   = threadIdx.x;

    for (int i = t; i < 1024; i += 256) {
        s_hpn[i] = g_hpn[b * 1024 + i];
        s_vpn[i] = g_vpn[b * 1024 + i];
    }
    __syncthreads();

    if (t < 128) {
        const int o = grp * 8 + (t >> 4);
        const int p = t & 15;
        float ah = 0.f, av = 0.f;
#pragma unroll 8
        for (int c = 0; c < 64; ++c) {
            ah += Wf[o * 128 + c]      * s_hpn[c * 16 + p];
            av += Wf[o * 128 + 64 + c] * s_vpn[c * 16 + p];
        }
        const float invf = fg[o] * rsqrtf(fvr[o] + 1e-5f);
        s_fh[t] = ah * invf;
        s_fv[t] = (av + bf[o]) * invf + (fb[o] - fm[o] * invf);
    }
    __syncthreads();

    // 8 channels x 16 x 16 = 2048 sigmoid entries; 8 per thread.
#pragma unroll
    for (int k = 0; k < 8; ++k) {
        const int i  = k * 256 + t;
        const int ch = i >> 8;
        const int p  = (i >> 4) & 15;
        const int q  = i & 15;
        const float z = s_fh[ch * 16 + p] + s_fv[ch * 16 + q];
        g_sig[(size_t)(b * 64 + grp * 8 + ch) * 256 + p * 16 + q] =
            1.0f / (1.0f + expf(-z));
    }
}

// ---------------------------------------------------------------------------
// Kernel 3: out = sig[bc, h>>4, w>>4] * x. Lean R3 form (22 regs), reverse
// block order + .cs reads (exploit pool-era L2 residency of x) and .wt
// write-through stores (do NOT allocate L2 -> keep x lines resident).
// ---------------------------------------------------------------------------
__global__ void __launch_bounds__(256) sp_gate_kernel(
    const float4* __restrict__ x4, float4* __restrict__ out4)
{
    const int rblk  = 4095 - blockIdx.x;
    const int plane = rblk >> 3;
    const int chunk = rblk & 7;
    const size_t base = (size_t)plane * 16384 + (size_t)chunk * 2048;

    const int t  = threadIdx.x;
    const int wb = (t & 63) >> 2;

    const float* __restrict__ sig = g_sig + plane * 256 + chunk * 32;
    const float s0 = __ldg(&sig[wb]);
    const float s1 = __ldg(&sig[16 + wb]);

#pragma unroll
    for (int j = 0; j < 8; ++j) {
        const size_t idx = base + j * 256 + t;
        float4 v = __ldcs(&x4[idx]);
        const float s = (j < 4) ? s0 : s1;
        v.x *= s; v.y *= s; v.z *= s; v.w *= s;
        __stwt(&out4[idx], v);
    }
}

// ---------------------------------------------------------------------------
extern "C" void kernel_launch(void* const* d_in, const int* in_sizes, int n_in,
                              void* d_out, int out_size)
{
    const float* x  = (const float*)d_in[0];
    const float* Wh = (const float*)d_in[1];
    const float* bh = (const float*)d_in[2];
    const float* Wv = (const float*)d_in[3];
    const float* bv = (const float*)d_in[4];
    const float* Wf = (const float*)d_in[5];
    const float* bf = (const float*)d_in[6];
    const float* hg = (const float*)d_in[7];
    const float* hb = (const float*)d_in[8];
    const float* hm = (const float*)d_in[9];
    const float* hv = (const float*)d_in[10];
    const float* vg = (const float*)d_in[11];
    const float* vb = (const float*)d_in[12];
    const float* vm = (const float*)d_in[13];
    const float* vv = (const float*)d_in[14];
    const float* fg = (const float*)d_in[15];
    const float* fb = (const float*)d_in[16];
    const float* fm = (const float*)d_in[17];
    const float* fv = (const float*)d_in[18];

    sp_pool_kernel<<<8192, 128>>>(x);
    sp_mix1_kernel<<<8, 1024>>>(Wh, bh, Wv, bv,
                                hg, hb, hm, hv,
                                vg, vb, vm, vv);
    sp_mix2_kernel<<<64, 256>>>(Wf, bf, fg, fb, fm, fv);
    sp_gate_kernel<<<4096, 256>>>((const float4*)x, (float4*)d_out);
}